// round 16
// baseline (speedup 1.0000x reference)
#include <cuda_runtime.h>
#include <cstdint>

// DTL loss: inputs [M,N] f32, targets [M] i32 -> scalar f32
//   pos = inputs[r, tgt[r]]
//   hard = top-num_hard of row with target masked to -inf
//   out = mean_r( (1-pos)^2 + 0.2 * mean((1+hard)^2) )
//
// Two-kernel decomposition:
//   A) dtl_filter: flat float4 stream over the whole matrix, no smem/barriers.
//      Values >= 2.0 (excluding the target slot) are pushed to per-row global
//      candidate buffers. Pure-bandwidth shape.
//   B) dtl_select: one CTA per row, candidates read from L2-warm buffers,
//      exact top-k via 8-bit radix refinement + rank select (raw positive
//      float bits are order-isomorphic). Exact full-row fallback when guards
//      fail. Fused last-CTA reduction; buffers self-reset for graph replay.

#define ATHREADS 256
#define AGRID    2048
#define BTHREADS 256
#define CAPR     384       // candidate slots per row (expect ~230, +10 sigma)
#define RANK_MAX 48
#define THRESH   2.0f
#define DELTA    0.2
#define MAXROWS  8192

__device__ unsigned g_cnt[MAXROWS];            // zero-init; B resets per run
__device__ unsigned g_cand[MAXROWS * CAPR];
__device__ double   g_rows[MAXROWS];
__device__ unsigned g_ticket;                  // zero-init; B resets per run

__device__ __forceinline__ unsigned f2key(unsigned u) {
    return u ^ (((unsigned)((int)u >> 31)) | 0x80000000u);
}
__device__ __forceinline__ float key2f(unsigned k) {
    unsigned u = (k & 0x80000000u) ? (k ^ 0x80000000u) : ~k;
    return __uint_as_float(u);
}

// exact flat-index -> (row, col) using double reciprocal + integer fixup
__device__ __forceinline__ void idx2rc(int i, int n, double inv_n,
                                       int& row, int& col) {
    row = (int)((double)i * inv_n);
    col = i - row * n;
    if (col < 0)  { row--; col += n; }
    if (col >= n) { row++; col -= n; }
}

// ---------------- Kernel A: pure streaming filter ----------------
__global__ void __launch_bounds__(ATHREADS) dtl_filter(
    const float* __restrict__ inputs,
    const int*   __restrict__ targets,
    int n, int nv4, int ntotal, double inv_n)
{
    const int stride = AGRID * ATHREADS;
    const float4* vp = reinterpret_cast<const float4*>(inputs);

#define DTL_ARM(v, jj)                                                    \
    do {                                                                  \
        float mx_ = fmaxf(fmaxf((v).x, (v).y), fmaxf((v).z, (v).w));      \
        if (mx_ >= THRESH) {                                              \
            float e_[4] = {(v).x, (v).y, (v).z, (v).w};                   \
            _Pragma("unroll")                                             \
            for (int q_ = 0; q_ < 4; q_++) {                              \
                if (e_[q_] >= THRESH) {                                   \
                    int i_ = 4 * (jj) + q_;                               \
                    int r_, c_;                                           \
                    idx2rc(i_, n, inv_n, r_, c_);                         \
                    if (c_ != __ldg(targets + r_)) {                      \
                        unsigned p_ = atomicAdd(&g_cnt[r_], 1u);          \
                        if (p_ < CAPR)                                    \
                            g_cand[r_ * CAPR + p_] =                      \
                                __float_as_uint(e_[q_]);                  \
                    }                                                     \
                }                                                         \
            }                                                             \
        }                                                                 \
    } while (0)

    int j = blockIdx.x * ATHREADS + threadIdx.x;
    for (; j + 3 * stride < nv4; j += 4 * stride) {
        float4 a = __ldg(vp + j);                  // 4 independent loads
        float4 b = __ldg(vp + j + stride);
        float4 c = __ldg(vp + j + 2 * stride);
        float4 d = __ldg(vp + j + 3 * stride);
        DTL_ARM(a, j);
        DTL_ARM(b, j + stride);
        DTL_ARM(c, j + 2 * stride);
        DTL_ARM(d, j + 3 * stride);
    }
    for (; j < nv4; j += stride) {
        float4 a = __ldg(vp + j);
        DTL_ARM(a, j);
    }
#undef DTL_ARM

    // scalar tail (ntotal % 4 elements)
    for (int i = 4 * nv4 + blockIdx.x * ATHREADS + threadIdx.x;
         i < ntotal; i += stride) {
        float x = __ldg(inputs + i);
        if (x >= THRESH) {
            int r, c;
            idx2rc(i, n, inv_n, r, c);
            if (c != __ldg(targets + r)) {
                unsigned p = atomicAdd(&g_cnt[r], 1u);
                if (p < CAPR) g_cand[r * CAPR + p] = __float_as_uint(x);
            }
        }
    }
}

// ---------------- Kernel B: per-row exact selection ----------------
__global__ void __launch_bounds__(BTHREADS) dtl_select(
    const float* __restrict__ inputs,
    const int*   __restrict__ targets,
    float* __restrict__ out,
    int m, int n, int num_hard)
{
    __shared__ unsigned candA[CAPR];
    __shared__ unsigned candB[CAPR];
    __shared__ unsigned hist[256];
    __shared__ int    s_cnt2, s_sel, s_k, s_last;
    __shared__ double warp_sums[BTHREADS / 32];
    __shared__ double red[BTHREADS];

    const int row  = blockIdx.x;
    const int tid  = threadIdx.x;
    const int lane = tid & 31;
    const int wid  = tid >> 5;
    const float* rowp = inputs + (size_t)row * (size_t)n;
    const int tgt = targets[row];

    const unsigned rawcnt = g_cnt[row];
    const int c = (int)min(rawcnt, (unsigned)CAPR);
    float pos_val = 0.0f;
    if (tid == 0) pos_val = __ldg(rowp + tgt);

    // load candidates into smem (L2-warm: kernel A just wrote them)
    for (int j = tid; j < c; j += BTHREADS)
        candA[j] = g_cand[row * CAPR + j];
    if (tid == 0) g_cnt[row] = 0u;          // self-reset for next replay
    __syncthreads();

    double acc = 0.0;

    if (num_hard > 0 && rawcnt <= (unsigned)CAPR && c >= num_hard) {
        // ---------- Common path: exact top-k among raw-bit keys ----------
        if (tid == 0) { s_k = num_hard; s_cnt2 = 0; }
        __syncthreads();

        int cc = c;
        unsigned* src = candA;
        unsigned* dst = candB;
        const int shifts4[4] = {24, 16, 8, 0};   // full 32-bit coverage
        for (int pi = 0; pi < 4 && cc > RANK_MAX; pi++) {
            const int sh = shifts4[pi];
            for (int i = tid; i < 256; i += BTHREADS) hist[i] = 0u;
            if (tid == 0) s_cnt2 = 0;
            __syncthreads();
            for (int j = tid; j < cc; j += BTHREADS)
                atomicAdd(&hist[(src[j] >> sh) & 255u], 1u);
            __syncthreads();
            if (wid == 0) {
                int k = s_k;
                unsigned bins[8]; unsigned t = 0u;
#pragma unroll
                for (int i = 0; i < 8; i++) { bins[i] = hist[lane * 8 + i]; t += bins[i]; }
                unsigned s = t;
#pragma unroll
                for (int o = 1; o < 32; o <<= 1) {
                    unsigned u = __shfl_down_sync(0xffffffffu, s, o);
                    if (lane + o < 32) s += u;
                }
                unsigned above = s - t;
#pragma unroll
                for (int b = 7; b >= 0; b--) {
                    if (above < (unsigned)k && (unsigned)k <= above + bins[b]) {
                        s_sel = lane * 8 + b;
                        s_k   = k - (int)above;
                    }
                    above += bins[b];
                }
            }
            __syncthreads();
            const unsigned sel2 = (unsigned)s_sel;
            for (int j = tid; j < cc; j += BTHREADS) {
                unsigned key = src[j];
                unsigned d = (key >> sh) & 255u;
                if (d > sel2) {
                    double t = 1.0 + (double)__uint_as_float(key);
                    acc += t * t;
                } else if (d == sel2) {
                    int p = atomicAdd(&s_cnt2, 1);
                    dst[p] = key;
                }
            }
            __syncthreads();
            cc = s_cnt2;
            unsigned* tmp = src; src = dst; dst = tmp;
        }
        // ---------- Exact rank select (index tie-break; ties equal)
        const int k = s_k;
        for (int j = tid; j < cc; j += BTHREADS) {
            unsigned mk = src[j];
            int r = 0;
            for (int t = 0; t < cc; t++) {
                unsigned o = src[t];
                r += (o > mk) || (o == mk && t < j);
            }
            if (r < k) {
                double t = 1.0 + (double)__uint_as_float(mk);
                acc += t * t;
            }
        }
    } else if (num_hard > 0) {
        // ---------- Exact fallback: full radix select over global row ------
        if (tid < 32) hist[tid] = 0u;
        __syncthreads();
        for (int col = tid; col < n; col += BTHREADS) {
            if (col == tgt) continue;
            unsigned key = f2key(__float_as_uint(__ldg(rowp + col)));
            atomicAdd(&hist[key >> 29], 1u);
        }
        __syncthreads();
        if (wid == 0) {
            int kk = num_hard;
            unsigned cc2 = (lane < 8) ? hist[lane] : 0u;
            unsigned s = cc2;
#pragma unroll
            for (int o = 1; o < 8; o <<= 1) {
                unsigned t = __shfl_down_sync(0xffffffffu, s, o);
                if (lane + o < 8) s += t;
            }
            unsigned above = s - cc2;
            if (lane < 8 && above < (unsigned)kk && (unsigned)kk <= s) {
                s_sel = (int)lane;
                s_k   = kk - (int)above;
            }
        }
        __syncthreads();
        unsigned pmask = 0xE0000000u;
        unsigned pval  = ((unsigned)s_sel) << 29;
        for (int col = tid; col < n; col += BTHREADS) {
            if (col == tgt) continue;
            unsigned key = f2key(__float_as_uint(__ldg(rowp + col)));
            if ((key >> 29) > (pval >> 29)) {
                double t = 1.0 + (double)key2f(key);
                acc += t * t;
            }
        }
        const int shifts[6] = {24, 19, 14, 9, 4, 0};
        for (int lv = 0; lv < 6; lv++) {
            const int sh = shifts[lv];
            const unsigned wmask = (lv == 5) ? 0xFu : 0x1Fu;
            if (tid < 32) hist[tid] = 0u;
            __syncthreads();
            for (int col = tid; col < n; col += BTHREADS) {
                if (col == tgt) continue;
                unsigned key = f2key(__float_as_uint(__ldg(rowp + col)));
                if ((key & pmask) == pval)
                    atomicAdd(&hist[(key >> sh) & wmask], 1u);
            }
            __syncthreads();
            if (wid == 0) {
                int kk = s_k;
                unsigned cc2 = hist[lane];
                unsigned s = cc2;
#pragma unroll
                for (int o = 1; o < 32; o <<= 1) {
                    unsigned t = __shfl_down_sync(0xffffffffu, s, o);
                    if (lane + o < 32) s += t;
                }
                unsigned above = s - cc2;
                if (above < (unsigned)kk && (unsigned)kk <= s) {
                    s_sel = (int)lane;
                    s_k   = kk - (int)above;
                }
            }
            __syncthreads();
            const unsigned dsel = (unsigned)s_sel;
            for (int col = tid; col < n; col += BTHREADS) {
                if (col == tgt) continue;
                unsigned key = f2key(__float_as_uint(__ldg(rowp + col)));
                if ((key & pmask) == pval && ((key >> sh) & wmask) > dsel) {
                    double t = 1.0 + (double)key2f(key);
                    acc += t * t;
                }
            }
            pval  |= dsel << sh;
            pmask |= wmask << sh;
            __syncthreads();
        }
        if (tid == 0) {
            double t = 1.0 + (double)key2f(pval);
            acc += (double)s_k * t * t;
        }
    }

    // ---------- Block reduction (double) + per-row result ----------
#pragma unroll
    for (int o = 16; o > 0; o >>= 1)
        acc += __shfl_down_sync(0xffffffffu, acc, o);
    if (lane == 0) warp_sums[wid] = acc;
    __syncthreads();
    if (tid == 0) {
        double tot = 0.0;
#pragma unroll
        for (int w = 0; w < BTHREADS / 32; w++) tot += warp_sums[w];
        double d1 = 1.0 - (double)pos_val;
        double hard = (num_hard > 0) ? tot / (double)num_hard : 0.0;
        g_rows[row] = d1 * d1 + DELTA * hard;
        __threadfence();
        unsigned old = atomicAdd(&g_ticket, 1u);
        s_last = (old == (unsigned)(m - 1)) ? 1 : 0;
    }
    __syncthreads();

    // ---------- Last CTA: fold per-row results into the scalar ----------
    if (s_last) {
        double s = 0.0;
        for (int i = tid; i < m; i += BTHREADS) s += g_rows[i];
        red[tid] = s;
        __syncthreads();
#pragma unroll
        for (int off = BTHREADS / 2; off > 0; off >>= 1) {
            if (tid < off) red[tid] += red[tid + off];
            __syncthreads();
        }
        if (tid == 0) {
            out[0] = (float)(red[0] / (double)m);
            g_ticket = 0u;               // reset for next graph replay
        }
    }
}

extern "C" void kernel_launch(void* const* d_in, const int* in_sizes, int n_in,
                              void* d_out, int out_size) {
    const float* inputs  = (const float*)d_in[0];
    const int*   targets = (const int*)d_in[1];
    int m = in_sizes[1];                    // rows (targets count)
    int n = in_sizes[0] / m;                // cols
    int num_hard = (int)(0.01 * (double)(n - 1));   // int(R*(n-1))
    if (m > MAXROWS) m = MAXROWS;           // safety (bench m = 4096)

    int ntotal = m * n;
    int nv4    = ntotal >> 2;
    double inv_n = 1.0 / (double)n;

    dtl_filter<<<AGRID, ATHREADS>>>(inputs, targets, n, nv4, ntotal, inv_n);
    dtl_select<<<m, BTHREADS>>>(inputs, targets, (float*)d_out, m, n, num_hard);
}

// round 17
// speedup vs baseline: 2.5454x; 2.5454x over previous
#include <cuda_runtime.h>
#include <cstdint>

// DTL loss: inputs [M,N] f32, targets [M] i32 -> scalar f32
//   pos = inputs[r, tgt[r]]
//   hard = top-num_hard of row with target masked to -inf
//   out = mean_r( (1-pos)^2 + 0.2 * mean((1+hard)^2) )
//
// One CTA per row, single launch. BRANCH-FREE candidate capture:
//   Pass A: count qualifiers (x >= 2.0, col != tgt) -- pure FSETP/IADD loop,
//           no atomics, no divergent arms -> DRAM-streaming shape.
//   Scan:   per-thread exclusive slots via shfl scan (no atomics).
//   Pass B: re-read row (L1/L2-warm), predicated 2-inst writes to smem slots.
// Exact top-k on raw positive float bits: 8-bit radix refinement + rank
// select; exact full-row fallback when guards fail. Fused last-CTA
// reduction; double accumulation throughout.

#define THREADS  256
#define NWARPS   (THREADS / 32)
#define CAP      1024
#define RANK_MAX 48
#define THRESH   2.0f
#define DELTA    0.2
#define MAXROWS  8192

__device__ double   g_rows[MAXROWS];
__device__ unsigned g_ticket;        // zero-init; last CTA resets per run

__device__ __forceinline__ unsigned f2key(unsigned u) {
    return u ^ (((unsigned)((int)u >> 31)) | 0x80000000u);
}
__device__ __forceinline__ float key2f(unsigned k) {
    unsigned u = (k & 0x80000000u) ? (k ^ 0x80000000u) : ~k;
    return __uint_as_float(u);
}

__global__ void __launch_bounds__(THREADS) dtl_kernel(
    const float* __restrict__ inputs,
    const int*   __restrict__ targets,
    float* __restrict__ out,
    int m, int n, int num_hard)
{
    __shared__ unsigned candA[CAP];
    __shared__ unsigned candB[CAP];
    __shared__ unsigned hist[256];
    __shared__ int    wtot[NWARPS];
    __shared__ int    s_cnt2, s_sel, s_k, s_last;
    __shared__ double warp_sums[NWARPS];
    __shared__ double red[THREADS];

    const int row  = blockIdx.x;
    const int tid  = threadIdx.x;
    const int lane = tid & 31;
    const int wid  = tid >> 5;
    const float* rowp = inputs + (size_t)row * (size_t)n;
    const int tgt = targets[row];

    float pos_val = 0.0f;               // used by tid 0 only
    if (tid == 0) pos_val = __ldg(rowp + tgt);

    // Alignment split: head scalars to 16B boundary, float4 body, tail.
    const int off4 = (int)(((uintptr_t)rowp >> 2) & 3u);
    int head = (4 - off4) & 3;
    if (head > n) head = n;
    const int nvec = (n - head) >> 2;
    const int nsca = n - 4 * nvec;       // head + tail scalars
    const float4* vp = reinterpret_cast<const float4*>(rowp + head);

    // ---------- Pass A: branch-free count of qualifying elements ----------
    int cnt = 0;
    {
#define DTL_CNT(v, jj)                                                    \
        do {                                                              \
            int base_ = head + 4 * (jj);                                  \
            cnt += ((v).x >= THRESH && base_ + 0 != tgt);                 \
            cnt += ((v).y >= THRESH && base_ + 1 != tgt);                 \
            cnt += ((v).z >= THRESH && base_ + 2 != tgt);                 \
            cnt += ((v).w >= THRESH && base_ + 3 != tgt);                 \
        } while (0)

        int j = tid;
        for (; j + 3 * THREADS < nvec; j += 4 * THREADS) {
            float4 a = __ldg(vp + j);
            float4 b = __ldg(vp + j + THREADS);
            float4 c = __ldg(vp + j + 2 * THREADS);
            float4 d = __ldg(vp + j + 3 * THREADS);
            DTL_CNT(a, j);
            DTL_CNT(b, j + THREADS);
            DTL_CNT(c, j + 2 * THREADS);
            DTL_CNT(d, j + 3 * THREADS);
        }
        for (; j < nvec; j += THREADS) {
            float4 a = __ldg(vp + j);
            DTL_CNT(a, j);
        }
#undef DTL_CNT
        if (tid < nsca) {
            int col = (tid < head) ? tid : (4 * nvec + tid);
            float x = __ldg(rowp + col);
            cnt += (x >= THRESH && col != tgt);
        }
    }

    // ---------- Exclusive scan of per-thread counts (shfl + warp totals) ---
    int incl = cnt;
#pragma unroll
    for (int o = 1; o < 32; o <<= 1) {
        int t = __shfl_up_sync(0xffffffffu, incl, o);
        if (lane >= o) incl += t;
    }
    if (lane == 31) wtot[wid] = incl;
    __syncthreads();
    int woff = 0, total = 0;
#pragma unroll
    for (int w = 0; w < NWARPS; w++) {
        int t = wtot[w];
        if (w < wid) woff += t;
        total += t;
    }
    const int myslot = woff + incl - cnt;    // exclusive offset

    // ---------- Pass B: predicated slot writes (row is L1/L2-warm) ---------
    if (total <= CAP) {
        int slot = myslot;
#define DTL_WR(v, jj)                                                     \
        do {                                                              \
            int base_ = head + 4 * (jj);                                  \
            if ((v).x >= THRESH && base_ + 0 != tgt)                      \
                candA[slot++] = __float_as_uint((v).x);                   \
            if ((v).y >= THRESH && base_ + 1 != tgt)                      \
                candA[slot++] = __float_as_uint((v).y);                   \
            if ((v).z >= THRESH && base_ + 2 != tgt)                      \
                candA[slot++] = __float_as_uint((v).z);                   \
            if ((v).w >= THRESH && base_ + 3 != tgt)                      \
                candA[slot++] = __float_as_uint((v).w);                   \
        } while (0)

        for (int j = tid; j < nvec; j += THREADS) {
            float4 a = __ldg(vp + j);
            DTL_WR(a, j);
        }
#undef DTL_WR
        if (tid < nsca) {
            int col = (tid < head) ? tid : (4 * nvec + tid);
            float x = __ldg(rowp + col);
            if (x >= THRESH && col != tgt)
                candA[slot++] = __float_as_uint(x);
        }
    }
    __syncthreads();

    double acc = 0.0;

    if (num_hard > 0 && total >= num_hard && total <= CAP) {
        // ---------- Common path: exact top-k among raw-bit keys ----------
        // Positive floats: raw bit order == value order.
        if (tid == 0) { s_k = num_hard; s_cnt2 = 0; }
        __syncthreads();

        int cc = total;
        unsigned* src = candA;
        unsigned* dst = candB;
        const int shifts4[4] = {24, 16, 8, 0};
        for (int pi = 0; pi < 4 && cc > RANK_MAX; pi++) {
            const int sh = shifts4[pi];
            for (int i = tid; i < 256; i += THREADS) hist[i] = 0u;
            if (tid == 0) s_cnt2 = 0;
            __syncthreads();
            for (int j = tid; j < cc; j += THREADS)
                atomicAdd(&hist[(src[j] >> sh) & 255u], 1u);
            __syncthreads();
            if (wid == 0) {
                int k = s_k;
                unsigned bins[8]; unsigned t = 0u;
#pragma unroll
                for (int i = 0; i < 8; i++) { bins[i] = hist[lane * 8 + i]; t += bins[i]; }
                unsigned s = t;
#pragma unroll
                for (int o = 1; o < 32; o <<= 1) {
                    unsigned u = __shfl_down_sync(0xffffffffu, s, o);
                    if (lane + o < 32) s += u;
                }
                unsigned above = s - t;      // count in strictly higher lanes
#pragma unroll
                for (int b = 7; b >= 0; b--) {
                    if (above < (unsigned)k && (unsigned)k <= above + bins[b]) {
                        s_sel = lane * 8 + b;
                        s_k   = k - (int)above;
                    }
                    above += bins[b];
                }
            }
            __syncthreads();
            const unsigned sel2 = (unsigned)s_sel;
            for (int j = tid; j < cc; j += THREADS) {
                unsigned key = src[j];
                unsigned d = (key >> sh) & 255u;
                if (d > sel2) {
                    double t = 1.0 + (double)__uint_as_float(key);
                    acc += t * t;
                } else if (d == sel2) {
                    int p = atomicAdd(&s_cnt2, 1);
                    dst[p] = key;
                }
            }
            __syncthreads();
            cc = s_cnt2;
            unsigned* tmp = src; src = dst; dst = tmp;
        }
        // ---------- Exact rank select (index tie-break; ties equal-valued)
        const int k = s_k;
        for (int j = tid; j < cc; j += THREADS) {
            unsigned mk = src[j];
            int r = 0;
            for (int t = 0; t < cc; t++) {
                unsigned o = src[t];
                r += (o > mk) || (o == mk && t < j);
            }
            if (r < k) {
                double t = 1.0 + (double)__uint_as_float(mk);
                acc += t * t;
            }
        }
    } else if (num_hard > 0) {
        // ---------- Exact fallback: full radix select over global row ------
        if (tid < 32) hist[tid] = 0u;
        __syncthreads();
        for (int col = tid; col < n; col += THREADS) {
            if (col == tgt) continue;
            unsigned key = f2key(__float_as_uint(__ldg(rowp + col)));
            atomicAdd(&hist[key >> 29], 1u);
        }
        __syncthreads();
        if (wid == 0) {
            int kk = num_hard;
            unsigned cc2 = (lane < 8) ? hist[lane] : 0u;
            unsigned s = cc2;
#pragma unroll
            for (int o = 1; o < 8; o <<= 1) {
                unsigned t = __shfl_down_sync(0xffffffffu, s, o);
                if (lane + o < 8) s += t;
            }
            unsigned above = s - cc2;
            if (lane < 8 && above < (unsigned)kk && (unsigned)kk <= s) {
                s_sel = (int)lane;
                s_k   = kk - (int)above;
            }
        }
        __syncthreads();
        unsigned pmask = 0xE0000000u;
        unsigned pval  = ((unsigned)s_sel) << 29;
        for (int col = tid; col < n; col += THREADS) {
            if (col == tgt) continue;
            unsigned key = f2key(__float_as_uint(__ldg(rowp + col)));
            if ((key >> 29) > (pval >> 29)) {
                double t = 1.0 + (double)key2f(key);
                acc += t * t;
            }
        }
        const int shifts[6] = {24, 19, 14, 9, 4, 0};
        for (int lv = 0; lv < 6; lv++) {
            const int sh = shifts[lv];
            const unsigned wmask = (lv == 5) ? 0xFu : 0x1Fu;
            if (tid < 32) hist[tid] = 0u;
            __syncthreads();
            for (int col = tid; col < n; col += THREADS) {
                if (col == tgt) continue;
                unsigned key = f2key(__float_as_uint(__ldg(rowp + col)));
                if ((key & pmask) == pval)
                    atomicAdd(&hist[(key >> sh) & wmask], 1u);
            }
            __syncthreads();
            if (wid == 0) {
                int kk = s_k;
                unsigned cc2 = hist[lane];
                unsigned s = cc2;
#pragma unroll
                for (int o = 1; o < 32; o <<= 1) {
                    unsigned t = __shfl_down_sync(0xffffffffu, s, o);
                    if (lane + o < 32) s += t;
                }
                unsigned above = s - cc2;
                if (above < (unsigned)kk && (unsigned)kk <= s) {
                    s_sel = (int)lane;
                    s_k   = kk - (int)above;
                }
            }
            __syncthreads();
            const unsigned dsel = (unsigned)s_sel;
            for (int col = tid; col < n; col += THREADS) {
                if (col == tgt) continue;
                unsigned key = f2key(__float_as_uint(__ldg(rowp + col)));
                if ((key & pmask) == pval && ((key >> sh) & wmask) > dsel) {
                    double t = 1.0 + (double)key2f(key);
                    acc += t * t;
                }
            }
            pval  |= dsel << sh;
            pmask |= wmask << sh;
            __syncthreads();
        }
        if (tid == 0) {      // remaining s_k elements equal pval exactly
            double t = 1.0 + (double)key2f(pval);
            acc += (double)s_k * t * t;
        }
    }

    // ---------- Block reduction (double) + per-row result ----------
#pragma unroll
    for (int o = 16; o > 0; o >>= 1)
        acc += __shfl_down_sync(0xffffffffu, acc, o);
    if (lane == 0) warp_sums[wid] = acc;
    __syncthreads();
    if (tid == 0) {
        double tot2 = 0.0;
#pragma unroll
        for (int w = 0; w < NWARPS; w++) tot2 += warp_sums[w];
        double d1 = 1.0 - (double)pos_val;
        double hard = (num_hard > 0) ? tot2 / (double)num_hard : 0.0;
        g_rows[row] = d1 * d1 + DELTA * hard;
        __threadfence();
        unsigned old = atomicAdd(&g_ticket, 1u);
        s_last = (old == (unsigned)(m - 1)) ? 1 : 0;
    }
    __syncthreads();

    // ---------- Last CTA: fold per-row results into the scalar ----------
    if (s_last) {
        double s = 0.0;
        for (int i = tid; i < m; i += THREADS) s += g_rows[i];
        red[tid] = s;
        __syncthreads();
#pragma unroll
        for (int off = THREADS / 2; off > 0; off >>= 1) {
            if (tid < off) red[tid] += red[tid + off];
            __syncthreads();
        }
        if (tid == 0) {
            out[0] = (float)(red[0] / (double)m);
            g_ticket = 0u;               // reset for next graph replay
        }
    }
}

extern "C" void kernel_launch(void* const* d_in, const int* in_sizes, int n_in,
                              void* d_out, int out_size) {
    const float* inputs  = (const float*)d_in[0];
    const int*   targets = (const int*)d_in[1];
    int m = in_sizes[1];                    // rows (targets count)
    int n = in_sizes[0] / m;                // cols
    int num_hard = (int)(0.01 * (double)(n - 1));   // int(R*(n-1))
    if (m > MAXROWS) m = MAXROWS;           // safety (bench m = 4096)

    dtl_kernel<<<m, THREADS>>>(inputs, targets, (float*)d_out, m, n, num_hard);
}